// round 16
// baseline (speedup 1.0000x reference)
#include <cuda_runtime.h>
#include <math.h>

// Fixed problem shape (from reference setup_inputs): B=8, T=256, U=65, V=1024
#define BB 8
#define TT 256
#define UU 65
#define VV 1024
#define SRG 392             // padded global row stride (words); data at [OFF, OFF+256)
#define OFF 66              // covers t index range [-66, 325]
#define NG  64              // t-groups of 4 per batch
#define CNT_FULL 260u       // 65 rows * 4 columns per group
#define LOG2E 1.4426950408889634f
#define LN2   0.6931471805599453f

// Padded per-(b,u) rows, log2 domain. Pads are NEVER written -> stay 0.
__device__ float    g_lpb[BB * UU * SRG];
__device__ float    g_lpl[BB * UU * SRG];
__device__ unsigned g_grpcnt[BB * NG];   // per (b, t/4) completion counters
__device__ float    g_ll[BB];
__device__ int      g_cnt;

__device__ __forceinline__ float lae2(float x, float y)
{
    float m = fmaxf(x, y);
    return m + __log2f(1.0f + exp2f(-fabsf(x - y)));
}

// Advance lsc (last complete column) until >= c. Group-granular counter poll;
// resets each consumed counter to 0 for the next graph replay (sole reader).
__device__ __forceinline__ void wait_col(unsigned* cnts, int& lsc, int c)
{
    if (c > TT - 1) c = TT - 1;
    if (lsc >= c) return;
    do {
        int g = (lsc + 1) >> 2;
        unsigned r = *((volatile unsigned*)&cnts[g]);
        if (r == CNT_FULL) { cnts[g] = 0u; lsc = g * 4 + 3; }
    } while (lsc < c);
    __threadfence();            // acquire: order data loads after counter obs.
}

__global__ __launch_bounds__(256) void rnnt_fused_kernel(
    const float* __restrict__ acts,
    const int*   __restrict__ labels,
    const int*   __restrict__ act_lens,
    const int*   __restrict__ label_lens,
    float* __restrict__ out)
{
    if (blockIdx.x >= BB) {
        // ------------------ softmax producer (t-major order) ------------------
        int warp = (int)(blockIdx.x - BB) * 8 + ((int)threadIdx.x >> 5);
        int lane = threadIdx.x & 31;
        int t = warp / (BB * UU);
        int r = warp - t * (BB * UU);
        int b = r / UU;
        int u = r - b * UU;

        const float* rowp = acts + ((size_t)(b * TT + t) * UU + u) * VV;

        bool  has_lbl = (u < UU - 1);
        float lblv = 0.f;
        if (has_lbl)
            lblv = __ldg(rowp + labels[b * (UU - 1) + u]);

        const float4* row4 = reinterpret_cast<const float4*>(rowp);
        float s0 = 0.f, s1 = 0.f, s2 = 0.f, s3 = 0.f, blank = 0.f;
#pragma unroll
        for (int k = 0; k < 8; k++) {
            float4 v = __ldcs(row4 + k * 32 + lane);
            if (k == 0) blank = v.x;             // element 0 lives in lane 0
            s0 += __expf(v.x);
            s1 += __expf(v.y);
            s2 += __expf(v.z);
            s3 += __expf(v.w);
        }
        float s = (s0 + s1) + (s2 + s3);
#pragma unroll
        for (int o = 16; o > 0; o >>= 1)
            s += __shfl_xor_sync(0xffffffffu, s, o);
        float lse2 = __log2f(s);

        if (lane == 0) {
            int base = (b * UU + u) * SRG + OFF + t;
            g_lpb[base] = fmaf(blank, LOG2E, -lse2);
            if (has_lbl)
                g_lpl[base] = fmaf(lblv, LOG2E, -lse2);
            __threadfence();                     // release before counter bump
            atomicAdd(&g_grpcnt[b * NG + (t >> 2)], 1u);
        }
        return;
    }

    // ------------------ alpha chaser (warp 0 of blocks 0..7) ------------------
    if (threadIdx.x >= 32) return;
    const unsigned FULL = 0xffffffffu;
    const int b    = blockIdx.x;
    const int lane = threadIdx.x;
    const int Tb = act_lens[b];
    const int Ub = label_lens[b];
    const int u0 = lane, u1 = lane + 32;
    const bool lane0 = (lane == 0);

    // Loop-invariant global row bases: every access is [base + d], __ldcg only
    // (L1 bypass is required: lines are filled incrementally by other SMs).
    const float* gb0 = g_lpb + (b * UU + u0) * SRG + OFF - u0 - 1;
    const float* gl0 = g_lpl + (b * UU + max(u0 - 1, 0)) * SRG + OFF - u0;
    const float* gb1 = g_lpb + (b * UU + u1) * SRG + OFF - u1 - 1;
    const float* gl1 = g_lpl + (b * UU + u1 - 1) * SRG + OFF - u1;
    const float* gb2 = g_lpb + (b * UU + 64) * SRG + OFF - 65;
    const float* gl2 = g_lpl + (b * UU + 63) * SRG + OFF - 64;

    unsigned* cnts = g_grpcnt + b * NG;
    int lsc = -1;

    const int capD  = Tb - 1 + Ub;
    const int capd0 = (Ub == u0) ? capD : -1;
    const int capd1 = (Ub == u1) ? capD : -1;
    const int capd2 = (Ub == 64 && lane0) ? capD : -1;

    float a0 = 0.f, a1 = 0.f, a2 = 0.f, llreg = 0.f;

    // 2-deep operand pipeline (covers L2 latency in the tail).
    wait_col(cnts, lsc, 0);
    float b0c = __ldcg(gb0 + 0), l0c = __ldcg(gl0 + 0), b1c = __ldcg(gb1 + 0),
          l1c = __ldcg(gl1 + 0), b2c = __ldcg(gb2 + 0), l2c = __ldcg(gl2 + 0);
    wait_col(cnts, lsc, 1);
    float b0n = __ldcg(gb0 + 1), l0n = __ldcg(gl0 + 1), b1n = __ldcg(gb1 + 1),
          l1n = __ldcg(gl1 + 1), b2n = __ldcg(gb2 + 1), l2n = __ldcg(gl2 + 1);

    for (int d = 0; d < TT + UU - 1; d++) {
        // prev-diagonal cross-lane values (read BEFORE updates)
        float lf0   = __shfl_up_sync(FULL, a0, 1);   // a(u0-1) prev
        float lf1s  = __shfl_up_sync(FULL, a1, 1);   // a(u1-1) prev (lane>=1)
        float a0_31 = __shfl_sync(FULL, a0, 31);     // a(31) prev (left of u=32)
        float a1_31 = __shfl_sync(FULL, a1, 31);     // a(63) prev (left of u=64)
        float lf1 = lane0 ? a0_31 : lf1s;

        // prefetch operands for step d+2 (gated on column readiness)
        wait_col(cnts, lsc, d + 2);
        float b0f = __ldcg(gb0 + d + 2), l0f = __ldcg(gl0 + d + 2),
              b1f = __ldcg(gb1 + d + 2), l1f = __ldcg(gl1 + d + 2),
              b2f = __ldcg(gb2 + d + 2), l2f = __ldcg(gl2 + d + 2);

        // ---- cell u0 = lane ----
        {
            float x = a0 + b0c;
            float y = lf0 + l0c;
            float z = lae2(x, y);
            z = lane0 ? x : z;                       // u==0 row: blank path only
            float y0 = lane0 ? 0.f : y;              // t==0 init (0 at origin)
            float v = (d == u0) ? y0 : z;
            llreg = (d == capd0) ? v : llreg;
            a0 = v;
        }
        // ---- cell u1 = lane+32 ----
        {
            float x = a1 + b1c;
            float y = lf1 + l1c;
            float z = lae2(x, y);
            float v = (d == u1) ? y : z;
            llreg = (d == capd1) ? v : llreg;
            a1 = v;
        }
        // ---- cell u2 = 64 (all lanes identical; lane 0 owns capture) ----
        {
            float x = a2 + b2c;
            float y = a1_31 + l2c;
            float z = lae2(x, y);
            float v = (d == 64) ? y : z;
            llreg = (d == capd2) ? v : llreg;
            a2 = v;
        }

        b0c = b0n; l0c = l0n; b1c = b1n; l1c = l1n; b2c = b2n; l2c = l2n;
        b0n = b0f; l0n = l0f; b1n = b1f; l1n = l1f; b2n = b2f; l2n = l2f;
    }

    // Exactly one lane captured alpha(Tb-1,Ub); sum to all lanes.
#pragma unroll
    for (int o = 16; o > 0; o >>= 1)
        llreg += __shfl_xor_sync(FULL, llreg, o);

    if (lane == 0) {
        float ll = llreg + __ldcg(&g_lpb[(b * UU + Ub) * SRG + OFF + Tb - 1]);
        g_ll[b] = ll * LN2;                          // back to natural log
        __threadfence();
        int prev = atomicAdd(&g_cnt, 1);
        if (prev == BB - 1) {                        // last block: reduce + out
            float ssum = 0.f;
            for (int i = 0; i < BB; i++)
                ssum += *((volatile float*)&g_ll[i]);
            out[0] = -ssum / (float)BB;
            g_cnt = 0;                               // reset for next replay
        }
    }
}

extern "C" void kernel_launch(void* const* d_in, const int* in_sizes, int n_in,
                              void* d_out, int out_size)
{
    const float* acts       = (const float*)d_in[0];
    const int*   labels     = (const int*)d_in[1];
    const int*   act_lens   = (const int*)d_in[2];
    const int*   label_lens = (const int*)d_in[3];

    // 8 alpha blocks (scheduled first -> resident before producers finish)
    // + 16640 softmax blocks (8 row-warps each).
    int nblk = BB + (BB * TT * UU) / 8;              // 16648
    rnnt_fused_kernel<<<nblk, 256>>>(acts, labels, act_lens, label_lens,
                                     (float*)d_out);
}